// round 4
// baseline (speedup 1.0000x reference)
#include <cuda_runtime.h>
#include <math.h>

#define HWSZ 65536
#define NB 8
#define NPIX (NB * HWSZ)
#define CAP 16384
#define CAND_T 0.40f

__device__ float g_wmap[NPIX];          // scratch: wmap per pixel (2 MB)
__device__ float g_w[224];              // [0:64) w_score, [64:224) conv weights
__device__ float g_cand_val[NB * CAP];  // candidate scores per batch
__device__ int   g_cand_idx[NB * CAP];  // candidate global pixel index
__device__ int   g_cand_cnt[NB];
__device__ float g_thresh[NB];          // 10th-largest score per batch (-INF if <10 cands)

// ---------------------------------------------------------------------------
// Prep: fold w_bbx into w_width; reset candidate counters (every replay).
// ---------------------------------------------------------------------------
__global__ void prep_weights(const float* __restrict__ w_bbx,
                             const float* __restrict__ w_width,
                             const float* __restrict__ w_score) {
    int t = threadIdx.x;
    if (t < 64) g_w[t] = w_score[t];
    if (t < 160) {
        int i = t / 5;
        g_w[64 + t] = w_bbx[2 * i] * w_width[t];
    }
    if (t < NB) g_cand_cnt[t] = 0;
}

// ---------------------------------------------------------------------------
// Zero-fill out_box + out_m regions (6*NPIX contiguous floats).
// ---------------------------------------------------------------------------
__global__ void __launch_bounds__(256) k_zero(float* __restrict__ p) {
    size_t i = ((size_t)blockIdx.x * 256 + threadIdx.x) * 4;
    *(float4*)(p + i) = make_float4(0.f, 0.f, 0.f, 0.f);
}

// ---------------------------------------------------------------------------
// Kernel 1: score (64-ch dot) + wmap (max over 32 even chans, 5-tap h-conv).
// Thread = 4 consecutive pixels. Tail: warp-scan append of candidates
// (score > 0.40) to per-batch global list.
// ---------------------------------------------------------------------------
__global__ void __launch_bounds__(256, 4) k_score_wmap(
    const float* __restrict__ color, float* __restrict__ score_out) {
    __shared__ float ws[64];
    __shared__ float cwt[160];
    int t = threadIdx.x;
    if (t < 64) ws[t] = g_w[t];
    if (t < 160) cwt[t] = g_w[64 + t];
    __syncthreads();

    int p4 = (blockIdx.x * 256 + t) * 4;       // first of 4 pixels
    int b  = p4 >> 16;
    int hw = p4 & (HWSZ - 1);
    int w0 = hw & 255;
    const float* base = color + ((size_t)b * 64) * HWSZ + hw;

    float4 s = make_float4(0.f, 0.f, 0.f, 0.f);
    float m0 = -INFINITY, m1 = -INFINITY, m2 = -INFINITY, m3 = -INFINITY;
    const bool hasL = (w0 != 0), hasR = (w0 != 252);

#pragma unroll 4
    for (int i = 0; i < 32; i++) {
        const float* pe = base + (size_t)(2 * i) * HWSZ;
        float4 A = *(const float4*)pe;             // even channel
        float4 O = *(const float4*)(pe + HWSZ);    // odd channel
        float we = ws[2 * i], wo = ws[2 * i + 1];
        s.x = fmaf(A.x, we, fmaf(O.x, wo, s.x));
        s.y = fmaf(A.y, we, fmaf(O.y, wo, s.y));
        s.z = fmaf(A.z, we, fmaf(O.z, wo, s.z));
        s.w = fmaf(A.w, we, fmaf(O.w, wo, s.w));

        float2 L = hasL ? *(const float2*)(pe - 2) : make_float2(0.f, 0.f);
        float2 R = hasR ? *(const float2*)(pe + 4) : make_float2(0.f, 0.f);
        float c0 = cwt[5 * i], c1 = cwt[5 * i + 1], c2 = cwt[5 * i + 2],
              c3 = cwt[5 * i + 3], c4 = cwt[5 * i + 4];
        m0 = fmaxf(m0, L.x * c0 + L.y * c1 + A.x * c2 + A.y * c3 + A.z * c4);
        m1 = fmaxf(m1, L.y * c0 + A.x * c1 + A.y * c2 + A.z * c3 + A.w * c4);
        m2 = fmaxf(m2, A.x * c0 + A.y * c1 + A.z * c2 + A.w * c3 + R.x * c4);
        m3 = fmaxf(m3, A.y * c0 + A.z * c1 + A.w * c2 + R.x * c3 + R.y * c4);
    }
    *(float4*)(score_out + p4) = s;
    *(float4*)(g_wmap + p4)    = make_float4(m0, m1, m2, m3);

    // ---- candidate append: scores > CAND_T ----
    int lane = t & 31;
    int p0 = s.x > CAND_T, p1 = s.y > CAND_T, p2 = s.z > CAND_T, p3 = s.w > CAND_T;
    int n = p0 + p1 + p2 + p3;
    int pre = n;
#pragma unroll
    for (int off = 1; off < 32; off <<= 1) {
        int v = __shfl_up_sync(0xffffffffu, pre, off);
        if (lane >= off) pre += v;
    }
    int total = __shfl_sync(0xffffffffu, pre, 31);
    if (total > 0) {
        int wbase = 0;
        if (lane == 31) wbase = atomicAdd(&g_cand_cnt[b], total);
        wbase = __shfl_sync(0xffffffffu, wbase, 31);
        int o = wbase + (pre - n);
        int ob = b * CAP;
        if (p0 && o < CAP) { g_cand_val[ob + o] = s.x; g_cand_idx[ob + o] = p4; }
        o += p0;
        if (p1 && o < CAP) { g_cand_val[ob + o] = s.y; g_cand_idx[ob + o] = p4 + 1; }
        o += p1;
        if (p2 && o < CAP) { g_cand_val[ob + o] = s.z; g_cand_idx[ob + o] = p4 + 2; }
        o += p2;
        if (p3 && o < CAP) { g_cand_val[ob + o] = s.w; g_cand_idx[ob + o] = p4 + 3; }
    }
}

// ---------------------------------------------------------------------------
// Kernel 2: per-batch 10th-largest among candidates. One block per batch,
// 10 rounds of argmax-and-destroy over the global candidate list (L2-hot).
// If cnt < 10, threshold = -INF (exact: every sg>0.6 pixel is then in top-10).
// ---------------------------------------------------------------------------
__global__ void __launch_bounds__(1024) k_thresh() {
    __shared__ float wvs[32];
    __shared__ int   wis[32];
    int t = threadIdx.x, b = blockIdx.x;
    int cnt = g_cand_cnt[b];
    if (cnt > CAP) cnt = CAP;
    if (cnt < 10) {
        if (t == 0) g_thresh[b] = -INFINITY;
        return;
    }
    float* vals = g_cand_val + b * CAP;
    int lane = t & 31, wid = t >> 5;

    for (int r = 0; r < 10; r++) {
        float v = -INFINITY; int vi = 0;
        for (int i = t; i < cnt; i += 1024) {
            float x = vals[i];
            if (x > v) { v = x; vi = i; }
        }
#pragma unroll
        for (int off = 16; off; off >>= 1) {
            float ov = __shfl_down_sync(0xffffffffu, v, off);
            int   oi = __shfl_down_sync(0xffffffffu, vi, off);
            if (ov > v) { v = ov; vi = oi; }
        }
        if (lane == 0) { wvs[wid] = v; wis[wid] = vi; }
        __syncthreads();
        if (t == 0) {
            float bv = wvs[0]; int bi = wis[0];
#pragma unroll
            for (int j = 1; j < 32; j++)
                if (wvs[j] > bv) { bv = wvs[j]; bi = wis[j]; }
            if (r == 9) g_thresh[b] = bv;
            else vals[bi] = -INFINITY;
        }
        __syncthreads();
    }
}

// ---------------------------------------------------------------------------
// Kernel 3: sparse finalize over candidate list. Writes only mask-passing
// pixels (out already zeroed).
// ---------------------------------------------------------------------------
__global__ void __launch_bounds__(256) k_finalize_sparse(
    float* __restrict__ out_box, float* __restrict__ out_m) {
    int slot = blockIdx.x * 256 + threadIdx.x;
    int b = slot / CAP, i = slot - b * CAP;
    int cnt = g_cand_cnt[b];
    if (cnt > CAP) cnt = CAP;
    if (i >= cnt) return;

    float scv = g_cand_val[b * CAP + i];
    if (scv == -INFINITY) scv = g_thresh[b];   // destroyed slots were top-9 values; re-fetch not possible
    int pix = g_cand_idx[b * CAP + i];
    // NOTE: destroyed slots: k_thresh overwrote 9 values with -INF. Recompute
    // from score output instead (score_out == d_out base, passed via out_box-NPIX*? )
    // -- handled below via g_scoreptr.
    float sg = 1.0f / (1.0f + expf(-scv));
    float t10 = g_thresh[b];
    bool m = ((scv >= t10) && (sg > 0.6f)) || (sg > 0.8f);
    if (!m) return;

    int hw = pix & (HWSZ - 1);
    float xg = (float)(hw & 255), yg = (float)(hw >> 8);
    float cw = expf(scv) * 10.0f;
    float ch = expf(g_wmap[pix]) * 10.0f;
    float x1 = floorf(xg - cw), x2 = ceilf(xg + cw);
    if (x1 < 0.0f || x2 > 256.0f) {
        float hv = fminf(256.0f - xg, xg);
        x1 = floorf(xg - hv); x2 = ceilf(xg + hv);
    }
    float y1 = floorf(yg - ch), y2 = ceilf(yg + ch);
    if (y1 < 0.0f || y2 > 256.0f) {
        float hh = fminf(256.0f - yg, yg);
        y1 = floorf(yg - hh); y2 = ceilf(yg + hh);
    }
    float* r = out_box + (size_t)pix * 5;
    r[0] = sg; r[1] = x1; r[2] = y1; r[3] = x2; r[4] = y2;
    out_m[pix] = 1.0f;
}

// ---------------------------------------------------------------------------
// Restore the 9 candidate values k_thresh destroyed (argmax-and-destroy) so
// k_finalize_sparse sees true scores: re-read from the score output.
// ---------------------------------------------------------------------------
__global__ void k_restore(const float* __restrict__ score) {
    // one warp per batch: fix any -INF slots among first min(cnt,CAP)
    int b = blockIdx.x;
    int t = threadIdx.x;
    int cnt = g_cand_cnt[b];
    if (cnt > CAP) cnt = CAP;
    for (int i = t; i < cnt; i += blockDim.x) {
        if (g_cand_val[b * CAP + i] == -INFINITY)
            g_cand_val[b * CAP + i] = score[g_cand_idx[b * CAP + i]];
    }
}

// ---------------------------------------------------------------------------
// Launch. Output layout: score[B*HW] | out[B*HW*5] | m[B*HW]  (all f32)
// ---------------------------------------------------------------------------
extern "C" void kernel_launch(void* const* d_in, const int* in_sizes, int n_in,
                              void* d_out, int out_size) {
    const float* color   = (const float*)d_in[1];
    const float* w_bbx   = (const float*)d_in[2];
    const float* w_width = (const float*)d_in[3];
    const float* w_score = (const float*)d_in[5];

    float* score   = (float*)d_out;
    float* out_box = score + NPIX;
    float* out_m   = out_box + (size_t)NPIX * 5;

    prep_weights<<<1, 256>>>(w_bbx, w_width, w_score);
    k_zero<<<(6 * NPIX) / 1024, 256>>>(out_box);
    k_score_wmap<<<NPIX / 1024, 256>>>(color, score);
    k_thresh<<<NB, 1024>>>();
    k_restore<<<NB, 256>>>(score);
    k_finalize_sparse<<<(NB * CAP) / 256, 256>>>(out_box, out_m);
}

// round 5
// speedup vs baseline: 1.4047x; 1.4047x over previous
#include <cuda_runtime.h>
#include <math.h>

#define HWSZ 65536
#define NB 8
#define NPIX (NB * HWSZ)
#define CAP 16384
#define CAND_T 0.40f

__device__ float g_wmap[NPIX];          // scratch: wmap per pixel (2 MB)
__device__ float g_w[224];              // [0:64) w_score, [64:224) conv weights
__device__ float g_cand_val[NB * CAP];  // candidate scores per batch
__device__ int   g_cand_idx[NB * CAP];  // candidate global pixel index
__device__ int   g_cand_cnt[NB];
__device__ float g_thresh[NB];          // 10th-largest score per batch

// ---------------------------------------------------------------------------
// Prep: fold w_bbx into w_width; reset candidate counters (every replay).
// ---------------------------------------------------------------------------
__global__ void prep_weights(const float* __restrict__ w_bbx,
                             const float* __restrict__ w_width,
                             const float* __restrict__ w_score) {
    int t = threadIdx.x;
    if (t < 64) g_w[t] = w_score[t];
    if (t < 160) {
        int i = t / 5;
        g_w[64 + t] = w_bbx[2 * i] * w_width[t];
    }
    if (t < NB) g_cand_cnt[t] = 0;
}

// ---------------------------------------------------------------------------
// Zero-fill out_box + out_m regions (6*NPIX contiguous floats).
// ---------------------------------------------------------------------------
__global__ void __launch_bounds__(256) k_zero(float* __restrict__ p) {
    size_t i = ((size_t)blockIdx.x * 256 + threadIdx.x) * 4;
    *(float4*)(p + i) = make_float4(0.f, 0.f, 0.f, 0.f);
}

// ---------------------------------------------------------------------------
// Kernel 1: score (64-ch dot) + wmap (max over 32 even chans, 5-tap h-conv).
// Thread = 4 consecutive pixels. 3 CTAs/SM (no spills). Tail: warp-scan
// append of candidates (score > 0.40) to per-batch global list.
// ---------------------------------------------------------------------------
__global__ void __launch_bounds__(256, 3) k_score_wmap(
    const float* __restrict__ color, float* __restrict__ score_out) {
    __shared__ float ws[64];
    __shared__ float cwt[160];
    int t = threadIdx.x;
    if (t < 64) ws[t] = g_w[t];
    if (t < 160) cwt[t] = g_w[64 + t];
    __syncthreads();

    int p4 = (blockIdx.x * 256 + t) * 4;       // first of 4 pixels
    int b  = p4 >> 16;
    int hw = p4 & (HWSZ - 1);
    int w0 = hw & 255;
    const float* base = color + ((size_t)b * 64) * HWSZ + hw;

    float4 s = make_float4(0.f, 0.f, 0.f, 0.f);
    float m0 = -INFINITY, m1 = -INFINITY, m2 = -INFINITY, m3 = -INFINITY;
    const bool hasL = (w0 != 0), hasR = (w0 != 252);

#pragma unroll 4
    for (int i = 0; i < 32; i++) {
        const float* pe = base + (size_t)(2 * i) * HWSZ;
        float4 A = *(const float4*)pe;             // even channel
        float4 O = *(const float4*)(pe + HWSZ);    // odd channel
        float we = ws[2 * i], wo = ws[2 * i + 1];
        s.x = fmaf(A.x, we, fmaf(O.x, wo, s.x));
        s.y = fmaf(A.y, we, fmaf(O.y, wo, s.y));
        s.z = fmaf(A.z, we, fmaf(O.z, wo, s.z));
        s.w = fmaf(A.w, we, fmaf(O.w, wo, s.w));

        float2 L = hasL ? *(const float2*)(pe - 2) : make_float2(0.f, 0.f);
        float2 R = hasR ? *(const float2*)(pe + 4) : make_float2(0.f, 0.f);
        float c0 = cwt[5 * i], c1 = cwt[5 * i + 1], c2 = cwt[5 * i + 2],
              c3 = cwt[5 * i + 3], c4 = cwt[5 * i + 4];
        m0 = fmaxf(m0, L.x * c0 + L.y * c1 + A.x * c2 + A.y * c3 + A.z * c4);
        m1 = fmaxf(m1, L.y * c0 + A.x * c1 + A.y * c2 + A.z * c3 + A.w * c4);
        m2 = fmaxf(m2, A.x * c0 + A.y * c1 + A.z * c2 + A.w * c3 + R.x * c4);
        m3 = fmaxf(m3, A.y * c0 + A.z * c1 + A.w * c2 + R.x * c3 + R.y * c4);
    }
    *(float4*)(score_out + p4) = s;
    *(float4*)(g_wmap + p4)    = make_float4(m0, m1, m2, m3);

    // ---- candidate append: scores > CAND_T ----
    int lane = t & 31;
    int p0 = s.x > CAND_T, p1 = s.y > CAND_T, p2 = s.z > CAND_T, p3 = s.w > CAND_T;
    int n = p0 + p1 + p2 + p3;
    int pre = n;
#pragma unroll
    for (int off = 1; off < 32; off <<= 1) {
        int v = __shfl_up_sync(0xffffffffu, pre, off);
        if (lane >= off) pre += v;
    }
    int total = __shfl_sync(0xffffffffu, pre, 31);
    if (total > 0) {
        int wbase = 0;
        if (lane == 31) wbase = atomicAdd(&g_cand_cnt[b], total);
        wbase = __shfl_sync(0xffffffffu, wbase, 31);
        int o = wbase + (pre - n);
        int ob = b * CAP;
        if (p0 && o < CAP) { g_cand_val[ob + o] = s.x; g_cand_idx[ob + o] = p4; }
        o += p0;
        if (p1 && o < CAP) { g_cand_val[ob + o] = s.y; g_cand_idx[ob + o] = p4 + 1; }
        o += p1;
        if (p2 && o < CAP) { g_cand_val[ob + o] = s.z; g_cand_idx[ob + o] = p4 + 2; }
        o += p2;
        if (p3 && o < CAP) { g_cand_val[ob + o] = s.w; g_cand_idx[ob + o] = p4 + 3; }
    }
}

// ---------------------------------------------------------------------------
// Kernel 2: per-batch exact 10th-largest among candidates.
// One global pass: each thread insertion-sorts its strided slice into a
// register top-10 (global top-10 is contained in the union), dumps to smem,
// then 10 rounds of argmax-and-destroy over smem only. Global values intact.
// ---------------------------------------------------------------------------
__global__ void __launch_bounds__(1024) k_thresh() {
    __shared__ float sv[10240];
    __shared__ float wvs[32];
    __shared__ int   wis[32];
    int t = threadIdx.x, b = blockIdx.x;
    int cnt = g_cand_cnt[b];
    if (cnt > CAP) cnt = CAP;
    if (cnt < 10) {
        if (t == 0) g_thresh[b] = -INFINITY;
        return;
    }
    const float* vals = g_cand_val + b * CAP;

    float top[10];
#pragma unroll
    for (int k = 0; k < 10; k++) top[k] = -INFINITY;
    for (int i = t; i < cnt; i += 1024) {
        float v = vals[i];
        if (v > top[9]) {
            top[9] = v;
#pragma unroll
            for (int k = 9; k > 0; k--) {
                if (top[k] > top[k - 1]) {
                    float tmp = top[k - 1]; top[k - 1] = top[k]; top[k] = tmp;
                }
            }
        }
    }
#pragma unroll
    for (int k = 0; k < 10; k++) sv[t * 10 + k] = top[k];
    __syncthreads();

    int lane = t & 31, wid = t >> 5;
    for (int r = 0; r < 10; r++) {
        float v = -INFINITY; int vi = t * 10;
#pragma unroll
        for (int j = 0; j < 10; j++) {
            float x = sv[t * 10 + j];
            if (x > v) { v = x; vi = t * 10 + j; }
        }
#pragma unroll
        for (int off = 16; off; off >>= 1) {
            float ov = __shfl_down_sync(0xffffffffu, v, off);
            int   oi = __shfl_down_sync(0xffffffffu, vi, off);
            if (ov > v) { v = ov; vi = oi; }
        }
        if (lane == 0) { wvs[wid] = v; wis[wid] = vi; }
        __syncthreads();
        if (t == 0) {
            float bv = wvs[0]; int bi = wis[0];
#pragma unroll
            for (int j = 1; j < 32; j++)
                if (wvs[j] > bv) { bv = wvs[j]; bi = wis[j]; }
            if (r == 9) g_thresh[b] = bv;
            else sv[bi] = -INFINITY;
        }
        __syncthreads();
    }
}

// ---------------------------------------------------------------------------
// Kernel 3: sparse finalize over candidate list. Writes only mask-passing
// pixels (out already zeroed).
// ---------------------------------------------------------------------------
__global__ void __launch_bounds__(256) k_finalize_sparse(
    float* __restrict__ out_box, float* __restrict__ out_m) {
    int slot = blockIdx.x * 256 + threadIdx.x;
    int b = slot / CAP, i = slot - b * CAP;
    int cnt = g_cand_cnt[b];
    if (cnt > CAP) cnt = CAP;
    if (i >= cnt) return;

    float scv = g_cand_val[b * CAP + i];
    int pix   = g_cand_idx[b * CAP + i];
    float sg  = 1.0f / (1.0f + expf(-scv));
    float t10 = g_thresh[b];
    bool m = ((scv >= t10) && (sg > 0.6f)) || (sg > 0.8f);
    if (!m) return;

    int hw = pix & (HWSZ - 1);
    float xg = (float)(hw & 255), yg = (float)(hw >> 8);
    float cw = expf(scv) * 10.0f;
    float ch = expf(g_wmap[pix]) * 10.0f;
    float x1 = floorf(xg - cw), x2 = ceilf(xg + cw);
    if (x1 < 0.0f || x2 > 256.0f) {
        float hv = fminf(256.0f - xg, xg);
        x1 = floorf(xg - hv); x2 = ceilf(xg + hv);
    }
    float y1 = floorf(yg - ch), y2 = ceilf(yg + ch);
    if (y1 < 0.0f || y2 > 256.0f) {
        float hh = fminf(256.0f - yg, yg);
        y1 = floorf(yg - hh); y2 = ceilf(yg + hh);
    }
    float* r = out_box + (size_t)pix * 5;
    r[0] = sg; r[1] = x1; r[2] = y1; r[3] = x2; r[4] = y2;
    out_m[pix] = 1.0f;
}

// ---------------------------------------------------------------------------
// Launch. Output layout: score[B*HW] | out[B*HW*5] | m[B*HW]  (all f32)
// ---------------------------------------------------------------------------
extern "C" void kernel_launch(void* const* d_in, const int* in_sizes, int n_in,
                              void* d_out, int out_size) {
    const float* color   = (const float*)d_in[1];
    const float* w_bbx   = (const float*)d_in[2];
    const float* w_width = (const float*)d_in[3];
    const float* w_score = (const float*)d_in[5];

    float* score   = (float*)d_out;
    float* out_box = score + NPIX;
    float* out_m   = out_box + (size_t)NPIX * 5;

    prep_weights<<<1, 256>>>(w_bbx, w_width, w_score);
    k_zero<<<(6 * NPIX) / 1024, 256>>>(out_box);
    k_score_wmap<<<NPIX / 1024, 256>>>(color, score);
    k_thresh<<<NB, 1024>>>();
    k_finalize_sparse<<<(NB * CAP) / 256, 256>>>(out_box, out_m);
}

// round 6
// speedup vs baseline: 1.6303x; 1.1606x over previous
#include <cuda_runtime.h>
#include <math.h>

#define HWSZ 65536
#define NB 8
#define NPIX (NB * HWSZ)
#define CAP 16384
#define CAND_T 0.40f
#define PARTS 16

__device__ float g_wmap[NPIX];          // scratch: wmap per pixel (2 MB)
__device__ float g_w[224];              // [0:64) w_score, [64:224) conv weights
__device__ float g_cand_val[NB * CAP];  // candidate scores per batch
__device__ int   g_cand_idx[NB * CAP];  // candidate global pixel index
__device__ int   g_cand_cnt[NB];
__device__ float g_part[NB * PARTS * 10]; // per-part sorted top-10
__device__ float g_thresh[NB];          // 10th-largest score per batch

// ---------------------------------------------------------------------------
// Prep: fold w_bbx into w_width; reset candidate counters (every replay).
// ---------------------------------------------------------------------------
__global__ void prep_weights(const float* __restrict__ w_bbx,
                             const float* __restrict__ w_width,
                             const float* __restrict__ w_score) {
    int t = threadIdx.x;
    if (t < 64) g_w[t] = w_score[t];
    if (t < 160) {
        int i = t / 5;
        g_w[64 + t] = w_bbx[2 * i] * w_width[t];
    }
    if (t < NB) g_cand_cnt[t] = 0;
}

// ---------------------------------------------------------------------------
// Kernel 1: blocks [0,512): score (64-ch dot) + wmap (5-tap h-conv max) for
// 4 consecutive pixels/thread; candidate append via warp-scan + atomic.
// Blocks [512,1024): zero-fill out_box|out_m (overlaps with compute wave).
// ---------------------------------------------------------------------------
__global__ void __launch_bounds__(256, 3) k_score_wmap(
    const float* __restrict__ color, float* __restrict__ score_out,
    float* __restrict__ zero_base) {
    int t = threadIdx.x;
    if (blockIdx.x >= 512) {                 // zero-fill path: 6144 floats/block
        float* p = zero_base + (size_t)(blockIdx.x - 512) * 6144 + t * 4;
        float4 z = make_float4(0.f, 0.f, 0.f, 0.f);
#pragma unroll
        for (int q = 0; q < 6; q++) *(float4*)(p + q * 1024) = z;
        return;
    }

    __shared__ float ws[64];
    __shared__ float cwt[160];
    if (t < 64) ws[t] = g_w[t];
    if (t < 160) cwt[t] = g_w[64 + t];
    __syncthreads();

    int p4 = (blockIdx.x * 256 + t) * 4;       // first of 4 pixels
    int b  = p4 >> 16;
    int hw = p4 & (HWSZ - 1);
    int w0 = hw & 255;
    const float* base = color + ((size_t)b * 64) * HWSZ + hw;

    float4 s = make_float4(0.f, 0.f, 0.f, 0.f);
    float m0 = -INFINITY, m1 = -INFINITY, m2 = -INFINITY, m3 = -INFINITY;
    const bool hasL = (w0 != 0), hasR = (w0 != 252);

#pragma unroll 4
    for (int i = 0; i < 32; i++) {
        const float* pe = base + (size_t)(2 * i) * HWSZ;
        float4 A = *(const float4*)pe;             // even channel
        float4 O = *(const float4*)(pe + HWSZ);    // odd channel
        float we = ws[2 * i], wo = ws[2 * i + 1];
        s.x = fmaf(A.x, we, fmaf(O.x, wo, s.x));
        s.y = fmaf(A.y, we, fmaf(O.y, wo, s.y));
        s.z = fmaf(A.z, we, fmaf(O.z, wo, s.z));
        s.w = fmaf(A.w, we, fmaf(O.w, wo, s.w));

        float2 L = hasL ? *(const float2*)(pe - 2) : make_float2(0.f, 0.f);
        float2 R = hasR ? *(const float2*)(pe + 4) : make_float2(0.f, 0.f);
        float c0 = cwt[5 * i], c1 = cwt[5 * i + 1], c2 = cwt[5 * i + 2],
              c3 = cwt[5 * i + 3], c4 = cwt[5 * i + 4];
        m0 = fmaxf(m0, L.x * c0 + L.y * c1 + A.x * c2 + A.y * c3 + A.z * c4);
        m1 = fmaxf(m1, L.y * c0 + A.x * c1 + A.y * c2 + A.z * c3 + A.w * c4);
        m2 = fmaxf(m2, A.x * c0 + A.y * c1 + A.z * c2 + A.w * c3 + R.x * c4);
        m3 = fmaxf(m3, A.y * c0 + A.z * c1 + A.w * c2 + R.x * c3 + R.y * c4);
    }
    *(float4*)(score_out + p4) = s;
    *(float4*)(g_wmap + p4)    = make_float4(m0, m1, m2, m3);

    // ---- candidate append: scores > CAND_T ----
    int lane = t & 31;
    int p0 = s.x > CAND_T, p1 = s.y > CAND_T, p2 = s.z > CAND_T, p3 = s.w > CAND_T;
    int n = p0 + p1 + p2 + p3;
    int pre = n;
#pragma unroll
    for (int off = 1; off < 32; off <<= 1) {
        int v = __shfl_up_sync(0xffffffffu, pre, off);
        if (lane >= off) pre += v;
    }
    int total = __shfl_sync(0xffffffffu, pre, 31);
    if (total > 0) {
        int wbase = 0;
        if (lane == 31) wbase = atomicAdd(&g_cand_cnt[b], total);
        wbase = __shfl_sync(0xffffffffu, wbase, 31);
        int o = wbase + (pre - n);
        int ob = b * CAP;
        if (p0 && o < CAP) { g_cand_val[ob + o] = s.x; g_cand_idx[ob + o] = p4; }
        o += p0;
        if (p1 && o < CAP) { g_cand_val[ob + o] = s.y; g_cand_idx[ob + o] = p4 + 1; }
        o += p1;
        if (p2 && o < CAP) { g_cand_val[ob + o] = s.z; g_cand_idx[ob + o] = p4 + 2; }
        o += p2;
        if (p3 && o < CAP) { g_cand_val[ob + o] = s.w; g_cand_idx[ob + o] = p4 + 3; }
    }
}

// ---------------------------------------------------------------------------
// Warp merge helper: each lane holds a sorted (desc) 10-list; 10 rounds of
// all-lane butterfly argmax over the heads; winner pops (static shift).
// Round values are the warp's sorted top-10; returns the 10th (last) value.
// emit(r, v) callback-free: caller inspects per-round value via pointer.
// ---------------------------------------------------------------------------
__device__ __forceinline__ float warp_merge10(float top[10], int lane,
                                              float* out10 /*may be null*/) {
    float last = -INFINITY;
#pragma unroll
    for (int r = 0; r < 10; r++) {
        float v = top[0]; int vi = lane;
#pragma unroll
        for (int off = 16; off; off >>= 1) {
            float ov = __shfl_xor_sync(0xffffffffu, v, off);
            int   oi = __shfl_xor_sync(0xffffffffu, vi, off);
            if (ov > v || (ov == v && oi < vi)) { v = ov; vi = oi; }
        }
        if (lane == vi) {
#pragma unroll
            for (int k = 0; k < 9; k++) top[k] = top[k + 1];
            top[9] = -INFINITY;
        }
        if (out10 && lane == 0) out10[r] = v;
        last = v;
    }
    return last;
}

// ---------------------------------------------------------------------------
// Kernel 2a: 16 blocks per batch; block computes sorted top-10 of its slice
// of the candidate list. One __syncthreads total; merges are shfl-only.
// ---------------------------------------------------------------------------
__global__ void __launch_bounds__(256) k_thresh1() {
    __shared__ float wtop[8 * 10];
    int blk = blockIdx.x;
    int b = blk >> 4, s = blk & 15;
    int cnt = g_cand_cnt[b];
    if (cnt > CAP) cnt = CAP;
    int chunk = (cnt + PARTS - 1) / PARTS;
    int lo = s * chunk, hi = min(lo + chunk, cnt);
    const float* vals = g_cand_val + b * CAP;
    int t = threadIdx.x, lane = t & 31, wid = t >> 5;

    float top[10];
#pragma unroll
    for (int k = 0; k < 10; k++) top[k] = -INFINITY;
    for (int i = lo + t; i < hi; i += 256) {
        float v = vals[i];
        if (v > top[9]) {
            top[9] = v;
#pragma unroll
            for (int k = 9; k > 0; k--) {
                if (top[k] > top[k - 1]) {
                    float tmp = top[k - 1]; top[k - 1] = top[k]; top[k] = tmp;
                }
            }
        }
    }
    warp_merge10(top, lane, &wtop[wid * 10]);   // warp top-10 -> smem (sorted)
    __syncthreads();

    if (wid == 0) {
        float m[10];
        if (lane < 8) {
#pragma unroll
            for (int k = 0; k < 10; k++) m[k] = wtop[lane * 10 + k];
        } else {
#pragma unroll
            for (int k = 0; k < 10; k++) m[k] = -INFINITY;
        }
        warp_merge10(m, lane, &g_part[blk * 10]);  // block top-10 (sorted)
    }
}

// ---------------------------------------------------------------------------
// Kernel 2b: one block; warp b merges batch b's 16 sorted 10-lists.
// 10th merged value = exact 10th-largest candidate (or -INF if cnt<10,
// which is semantically exact: all sg>0.6 pixels are then in the top-10).
// ---------------------------------------------------------------------------
__global__ void __launch_bounds__(256) k_thresh2() {
    int t = threadIdx.x, lane = t & 31, b = t >> 5;
    float m[10];
    if (lane < PARTS) {
#pragma unroll
        for (int k = 0; k < 10; k++) m[k] = g_part[(b * PARTS + lane) * 10 + k];
    } else {
#pragma unroll
        for (int k = 0; k < 10; k++) m[k] = -INFINITY;
    }
    float t10 = warp_merge10(m, lane, 0);
    if (lane == 0) g_thresh[b] = t10;
}

// ---------------------------------------------------------------------------
// Kernel 3: sparse finalize over candidate list. Writes only mask-passing
// pixels (out already zeroed by k1's zero blocks).
// ---------------------------------------------------------------------------
__global__ void __launch_bounds__(256) k_finalize_sparse(
    float* __restrict__ out_box, float* __restrict__ out_m) {
    int slot = blockIdx.x * 256 + threadIdx.x;
    int b = slot / CAP, i = slot - b * CAP;
    int cnt = g_cand_cnt[b];
    if (cnt > CAP) cnt = CAP;
    if (i >= cnt) return;

    float scv = g_cand_val[b * CAP + i];
    int pix   = g_cand_idx[b * CAP + i];
    float sg  = 1.0f / (1.0f + expf(-scv));
    float t10 = g_thresh[b];
    bool m = ((scv >= t10) && (sg > 0.6f)) || (sg > 0.8f);
    if (!m) return;

    int hw = pix & (HWSZ - 1);
    float xg = (float)(hw & 255), yg = (float)(hw >> 8);
    float cw = expf(scv) * 10.0f;
    float ch = expf(g_wmap[pix]) * 10.0f;
    float x1 = floorf(xg - cw), x2 = ceilf(xg + cw);
    if (x1 < 0.0f || x2 > 256.0f) {
        float hv = fminf(256.0f - xg, xg);
        x1 = floorf(xg - hv); x2 = ceilf(xg + hv);
    }
    float y1 = floorf(yg - ch), y2 = ceilf(yg + ch);
    if (y1 < 0.0f || y2 > 256.0f) {
        float hh = fminf(256.0f - yg, yg);
        y1 = floorf(yg - hh); y2 = ceilf(yg + hh);
    }
    float* r = out_box + (size_t)pix * 5;
    r[0] = sg; r[1] = x1; r[2] = y1; r[3] = x2; r[4] = y2;
    out_m[pix] = 1.0f;
}

// ---------------------------------------------------------------------------
// Launch. Output layout: score[B*HW] | out[B*HW*5] | m[B*HW]  (all f32)
// ---------------------------------------------------------------------------
extern "C" void kernel_launch(void* const* d_in, const int* in_sizes, int n_in,
                              void* d_out, int out_size) {
    const float* color   = (const float*)d_in[1];
    const float* w_bbx   = (const float*)d_in[2];
    const float* w_width = (const float*)d_in[3];
    const float* w_score = (const float*)d_in[5];

    float* score   = (float*)d_out;
    float* out_box = score + NPIX;
    float* out_m   = out_box + (size_t)NPIX * 5;

    prep_weights<<<1, 256>>>(w_bbx, w_width, w_score);
    k_score_wmap<<<1024, 256>>>(color, score, out_box);  // 512 compute + 512 zero
    k_thresh1<<<NB * PARTS, 256>>>();
    k_thresh2<<<1, 256>>>();
    k_finalize_sparse<<<(NB * CAP) / 256, 256>>>(out_box, out_m);
}

// round 7
// speedup vs baseline: 1.7708x; 1.0862x over previous
#include <cuda_runtime.h>
#include <math.h>

#define HWSZ 65536
#define NB 8
#define NPIX (NB * HWSZ)
#define CAND_T 0.40f
#define NCBLK 512                 // k1 compute blocks (64 per batch)
#define SEG 1024                  // candidate segment size per compute block

__device__ float g_wmap[NPIX];            // scratch: wmap per pixel (2 MB)
__device__ float g_seg_val[NCBLK * SEG];  // per-block candidate scores
__device__ int   g_seg_idx[NCBLK * SEG];  // per-block candidate pixel index
__device__ int   g_seg_cnt[NCBLK];
__device__ float g_part[NCBLK * 10];      // per-block sorted top-10 (all scores)

// ---------------------------------------------------------------------------
// Warp merge-pop: each lane holds a sorted (desc) D-list; 10 rounds of
// butterfly argmax over heads; winner pops. out10 (lane 0) gets sorted top-10.
// Returns the 10th value.
// ---------------------------------------------------------------------------
template <int D>
__device__ __forceinline__ float warp_merge_pop(float (&top)[D], int lane,
                                                float* out10) {
    float last = -INFINITY;
#pragma unroll
    for (int r = 0; r < 10; r++) {
        float v = top[0]; int vi = lane;
#pragma unroll
        for (int off = 16; off; off >>= 1) {
            float ov = __shfl_xor_sync(0xffffffffu, v, off);
            int   oi = __shfl_xor_sync(0xffffffffu, vi, off);
            if (ov > v || (ov == v && oi < vi)) { v = ov; vi = oi; }
        }
        if (lane == vi) {
#pragma unroll
            for (int k = 0; k < D - 1; k++) top[k] = top[k + 1];
            top[D - 1] = -INFINITY;
        }
        if (out10 && lane == 0) out10[r] = v;
        last = v;
    }
    return last;
}

// ---------------------------------------------------------------------------
// Kernel 1. Blocks [0,512): score + wmap for 4 px/thread; candidate append
// to per-block segment; block-exact sorted top-10 of its 1024 scores.
// Blocks [512,1024): zero-fill out_box|out_m.
// Weights folded in-block (no prep kernel).
// ---------------------------------------------------------------------------
__global__ void __launch_bounds__(256, 3) k_score_wmap(
    const float* __restrict__ color, const float* __restrict__ w_bbx,
    const float* __restrict__ w_width, const float* __restrict__ w_score,
    float* __restrict__ score_out, float* __restrict__ zero_base) {
    int t = threadIdx.x;
    if (blockIdx.x >= NCBLK) {               // zero-fill path: 6144 floats/block
        float* p = zero_base + (size_t)(blockIdx.x - NCBLK) * 6144 + t * 4;
        float4 z = make_float4(0.f, 0.f, 0.f, 0.f);
#pragma unroll
        for (int q = 0; q < 6; q++) *(float4*)(p + q * 1024) = z;
        return;
    }

    __shared__ float ws[64];
    __shared__ float cwt[160];
    __shared__ float wtop[8 * 10];
    __shared__ int   scnt;
    if (t == 0) scnt = 0;
    if (t < 64) ws[t] = w_score[t];
    if (t < 160) cwt[t] = w_bbx[2 * (t / 5)] * w_width[t];
    __syncthreads();

    int p4 = (blockIdx.x * 256 + t) * 4;
    int b  = p4 >> 16;
    int hw = p4 & (HWSZ - 1);
    int w0 = hw & 255;
    const float* base = color + ((size_t)b * 64) * HWSZ + hw;

    float4 s = make_float4(0.f, 0.f, 0.f, 0.f);
    float m0 = -INFINITY, m1 = -INFINITY, m2 = -INFINITY, m3 = -INFINITY;
    const bool hasL = (w0 != 0), hasR = (w0 != 252);

#pragma unroll 4
    for (int i = 0; i < 32; i++) {
        const float* pe = base + (size_t)(2 * i) * HWSZ;
        float4 A = *(const float4*)pe;             // even channel
        float4 O = *(const float4*)(pe + HWSZ);    // odd channel
        float we = ws[2 * i], wo = ws[2 * i + 1];
        s.x = fmaf(A.x, we, fmaf(O.x, wo, s.x));
        s.y = fmaf(A.y, we, fmaf(O.y, wo, s.y));
        s.z = fmaf(A.z, we, fmaf(O.z, wo, s.z));
        s.w = fmaf(A.w, we, fmaf(O.w, wo, s.w));

        float2 L = hasL ? *(const float2*)(pe - 2) : make_float2(0.f, 0.f);
        float2 R = hasR ? *(const float2*)(pe + 4) : make_float2(0.f, 0.f);
        float c0 = cwt[5 * i], c1 = cwt[5 * i + 1], c2 = cwt[5 * i + 2],
              c3 = cwt[5 * i + 3], c4 = cwt[5 * i + 4];
        m0 = fmaxf(m0, L.x * c0 + L.y * c1 + A.x * c2 + A.y * c3 + A.z * c4);
        m1 = fmaxf(m1, L.y * c0 + A.x * c1 + A.y * c2 + A.z * c3 + A.w * c4);
        m2 = fmaxf(m2, A.x * c0 + A.y * c1 + A.z * c2 + A.w * c3 + R.x * c4);
        m3 = fmaxf(m3, A.y * c0 + A.z * c1 + A.w * c2 + R.x * c3 + R.y * c4);
    }
    *(float4*)(score_out + p4) = s;
    *(float4*)(g_wmap + p4)    = make_float4(m0, m1, m2, m3);

    int lane = t & 31, wid = t >> 5;

    // ---- candidate append to per-block segment (smem counter, no resets) ----
    int p0 = s.x > CAND_T, p1 = s.y > CAND_T, p2 = s.z > CAND_T, p3 = s.w > CAND_T;
    int n = p0 + p1 + p2 + p3;
    int pre = n;
#pragma unroll
    for (int off = 1; off < 32; off <<= 1) {
        int v = __shfl_up_sync(0xffffffffu, pre, off);
        if (lane >= off) pre += v;
    }
    int total = __shfl_sync(0xffffffffu, pre, 31);
    if (total > 0) {
        int wbase = 0;
        if (lane == 31) wbase = atomicAdd(&scnt, total);
        wbase = __shfl_sync(0xffffffffu, wbase, 31);
        int o = blockIdx.x * SEG + wbase + (pre - n);
        if (p0) { g_seg_val[o] = s.x; g_seg_idx[o] = p4;     o++; }
        if (p1) { g_seg_val[o] = s.y; g_seg_idx[o] = p4 + 1; o++; }
        if (p2) { g_seg_val[o] = s.z; g_seg_idx[o] = p4 + 2; o++; }
        if (p3) { g_seg_val[o] = s.w; g_seg_idx[o] = p4 + 3; }
    }

    // ---- block-exact sorted top-10 of all 1024 scores ----
    float a0 = s.x, a1 = s.y, a2 = s.z, a3 = s.w, tmp;
    if (a1 > a0) { tmp = a0; a0 = a1; a1 = tmp; }
    if (a3 > a2) { tmp = a2; a2 = a3; a3 = tmp; }
    if (a2 > a0) { tmp = a0; a0 = a2; a2 = tmp; }
    if (a3 > a1) { tmp = a1; a1 = a3; a3 = tmp; }
    if (a2 > a1) { tmp = a1; a1 = a2; a2 = tmp; }
    float st[4] = {a0, a1, a2, a3};
    warp_merge_pop<4>(st, lane, &wtop[wid * 10]);
    __syncthreads();
    if (t == 0) g_seg_cnt[blockIdx.x] = scnt;
    if (wid == 0) {
        float m[10];
#pragma unroll
        for (int k = 0; k < 10; k++)
            m[k] = (lane < 8) ? wtop[lane * 10 + k] : -INFINITY;
        warp_merge_pop<10>(m, lane, &g_part[blockIdx.x * 10]);
    }
}

// ---------------------------------------------------------------------------
// Kernel 2: finalize. Block i handles k1-block i's candidate segment.
// Warps 0-1 merge the batch's 64 sorted top-10 lists -> exact t10 (shfl-only,
// redundant per block but parallel). Then sparse box writes.
// ---------------------------------------------------------------------------
__global__ void __launch_bounds__(256) k_finalize(
    float* __restrict__ out_box, float* __restrict__ out_m) {
    __shared__ float wlist[2][10];
    __shared__ float s_t10;
    int t = threadIdx.x, lane = t & 31, wid = t >> 5;
    int blk = blockIdx.x;
    int b = blk >> 6;                       // 64 compute blocks per batch

    if (wid < 2) {
        float m[10];
        const float* src = g_part + (b * 64 + wid * 32 + lane) * 10;
#pragma unroll
        for (int k = 0; k < 10; k++) m[k] = src[k];
        warp_merge_pop<10>(m, lane, &wlist[wid][0]);
    }
    __syncthreads();
    if (wid == 0) {
        float m[10];
#pragma unroll
        for (int k = 0; k < 10; k++)
            m[k] = (lane < 2) ? wlist[lane][k] : -INFINITY;
        float t10 = warp_merge_pop<10>(m, lane, 0);
        if (lane == 0) s_t10 = t10;
    }
    __syncthreads();

    float t10 = s_t10;
    int cnt = g_seg_cnt[blk];
    for (int i = t; i < cnt; i += 256) {
        float scv = g_seg_val[blk * SEG + i];
        float sg  = 1.0f / (1.0f + expf(-scv));
        bool m = ((scv >= t10) && (sg > 0.6f)) || (sg > 0.8f);
        if (!m) continue;
        int pix = g_seg_idx[blk * SEG + i];
        int hw = pix & (HWSZ - 1);
        float xg = (float)(hw & 255), yg = (float)(hw >> 8);
        float cw = expf(scv) * 10.0f;
        float ch = expf(g_wmap[pix]) * 10.0f;
        float x1 = floorf(xg - cw), x2 = ceilf(xg + cw);
        if (x1 < 0.0f || x2 > 256.0f) {
            float hv = fminf(256.0f - xg, xg);
            x1 = floorf(xg - hv); x2 = ceilf(xg + hv);
        }
        float y1 = floorf(yg - ch), y2 = ceilf(yg + ch);
        if (y1 < 0.0f || y2 > 256.0f) {
            float hh = fminf(256.0f - yg, yg);
            y1 = floorf(yg - hh); y2 = ceilf(yg + hh);
        }
        float* r = out_box + (size_t)pix * 5;
        r[0] = sg; r[1] = x1; r[2] = y1; r[3] = x2; r[4] = y2;
        out_m[pix] = 1.0f;
    }
}

// ---------------------------------------------------------------------------
// Launch. Output layout: score[B*HW] | out[B*HW*5] | m[B*HW]  (all f32)
// ---------------------------------------------------------------------------
extern "C" void kernel_launch(void* const* d_in, const int* in_sizes, int n_in,
                              void* d_out, int out_size) {
    const float* color   = (const float*)d_in[1];
    const float* w_bbx   = (const float*)d_in[2];
    const float* w_width = (const float*)d_in[3];
    const float* w_score = (const float*)d_in[5];

    float* score   = (float*)d_out;
    float* out_box = score + NPIX;
    float* out_m   = out_box + (size_t)NPIX * 5;

    k_score_wmap<<<1024, 256>>>(color, w_bbx, w_width, w_score, score, out_box);
    k_finalize<<<NCBLK, 256>>>(out_box, out_m);
}

// round 8
// speedup vs baseline: 1.7758x; 1.0028x over previous
#include <cuda_runtime.h>
#include <math.h>

#define HWSZ 65536
#define NB 8
#define NPIX (NB * HWSZ)
#define CAND_T 0.40f
#define NCBLK 512                 // k1 compute blocks (64 per batch)
#define SEG 1024                  // candidate segment size per compute block

__device__ float g_seg_val[NCBLK * SEG];  // per-block candidate scores
__device__ float g_seg_wm[NCBLK * SEG];   // per-block candidate wmap values
__device__ int   g_seg_idx[NCBLK * SEG];  // per-block candidate pixel index
__device__ int   g_seg_cnt[NCBLK];
__device__ float g_part[NCBLK * 10];      // per-block sorted top-10 (all scores)
__device__ int   g_done[NB];              // batch completion tickets (self-resetting)
__device__ float g_thresh[NB];            // exact 10th-largest score per batch

// ---------------------------------------------------------------------------
// Warp merge-pop: each lane holds a sorted (desc) D-list; 10 rounds of
// butterfly argmax over heads; winner pops. out10 (lane 0) gets sorted top-10.
// Returns the 10th value.
// ---------------------------------------------------------------------------
template <int D>
__device__ __forceinline__ float warp_merge_pop(float (&top)[D], int lane,
                                                float* out10) {
    float last = -INFINITY;
#pragma unroll
    for (int r = 0; r < 10; r++) {
        float v = top[0]; int vi = lane;
#pragma unroll
        for (int off = 16; off; off >>= 1) {
            float ov = __shfl_xor_sync(0xffffffffu, v, off);
            int   oi = __shfl_xor_sync(0xffffffffu, vi, off);
            if (ov > v || (ov == v && oi < vi)) { v = ov; vi = oi; }
        }
        if (lane == vi) {
#pragma unroll
            for (int k = 0; k < D - 1; k++) top[k] = top[k + 1];
            top[D - 1] = -INFINITY;
        }
        if (out10 && lane == 0) out10[r] = v;
        last = v;
    }
    return last;
}

// ---------------------------------------------------------------------------
// Kernel 1. Blocks [0,512): score + wmap for 4 px/thread; candidates
// (score, wmap, idx) -> per-block segment; block-exact sorted top-10 of all
// 1024 scores -> g_part. Last block of each batch merges the 64 lists ->
// g_thresh[b] (ticketed, overlapped with remaining compute).
// Blocks [512,1024): zero-fill out_box|out_m.
// ---------------------------------------------------------------------------
__global__ void __launch_bounds__(256, 3) k_score_wmap(
    const float* __restrict__ color, const float* __restrict__ w_bbx,
    const float* __restrict__ w_width, const float* __restrict__ w_score,
    float* __restrict__ score_out, float* __restrict__ zero_base) {
    int t = threadIdx.x;
    if (blockIdx.x >= NCBLK) {               // zero-fill path: 6144 floats/block
        float* p = zero_base + (size_t)(blockIdx.x - NCBLK) * 6144 + t * 4;
        float4 z = make_float4(0.f, 0.f, 0.f, 0.f);
#pragma unroll
        for (int q = 0; q < 6; q++) *(float4*)(p + q * 1024) = z;
        return;
    }

    __shared__ float ws[64];
    __shared__ float cwt[160];
    __shared__ float wtop[8 * 10];
    __shared__ float wlist[2][10];
    __shared__ int   scnt;
    __shared__ int   s_last;
    if (t == 0) scnt = 0;
    if (t < 64) ws[t] = w_score[t];
    if (t < 160) cwt[t] = w_bbx[2 * (t / 5)] * w_width[t];
    __syncthreads();

    int p4 = (blockIdx.x * 256 + t) * 4;
    int b  = p4 >> 16;
    int hw = p4 & (HWSZ - 1);
    int w0 = hw & 255;
    const float* base = color + ((size_t)b * 64) * HWSZ + hw;

    float4 s = make_float4(0.f, 0.f, 0.f, 0.f);
    float m0 = -INFINITY, m1 = -INFINITY, m2 = -INFINITY, m3 = -INFINITY;
    const bool hasL = (w0 != 0), hasR = (w0 != 252);

#pragma unroll 4
    for (int i = 0; i < 32; i++) {
        const float* pe = base + (size_t)(2 * i) * HWSZ;
        float4 A = *(const float4*)pe;             // even channel
        float4 O = *(const float4*)(pe + HWSZ);    // odd channel
        float we = ws[2 * i], wo = ws[2 * i + 1];
        s.x = fmaf(A.x, we, fmaf(O.x, wo, s.x));
        s.y = fmaf(A.y, we, fmaf(O.y, wo, s.y));
        s.z = fmaf(A.z, we, fmaf(O.z, wo, s.z));
        s.w = fmaf(A.w, we, fmaf(O.w, wo, s.w));

        float2 L = hasL ? *(const float2*)(pe - 2) : make_float2(0.f, 0.f);
        float2 R = hasR ? *(const float2*)(pe + 4) : make_float2(0.f, 0.f);
        float c0 = cwt[5 * i], c1 = cwt[5 * i + 1], c2 = cwt[5 * i + 2],
              c3 = cwt[5 * i + 3], c4 = cwt[5 * i + 4];
        m0 = fmaxf(m0, L.x * c0 + L.y * c1 + A.x * c2 + A.y * c3 + A.z * c4);
        m1 = fmaxf(m1, L.y * c0 + A.x * c1 + A.y * c2 + A.z * c3 + A.w * c4);
        m2 = fmaxf(m2, A.x * c0 + A.y * c1 + A.z * c2 + A.w * c3 + R.x * c4);
        m3 = fmaxf(m3, A.y * c0 + A.z * c1 + A.w * c2 + R.x * c3 + R.y * c4);
    }
    *(float4*)(score_out + p4) = s;

    int lane = t & 31, wid = t >> 5;

    // ---- candidate append (score > CAND_T): store score, wmap, idx ----
    int p0 = s.x > CAND_T, p1 = s.y > CAND_T, p2 = s.z > CAND_T, p3 = s.w > CAND_T;
    int n = p0 + p1 + p2 + p3;
    int pre = n;
#pragma unroll
    for (int off = 1; off < 32; off <<= 1) {
        int v = __shfl_up_sync(0xffffffffu, pre, off);
        if (lane >= off) pre += v;
    }
    int total = __shfl_sync(0xffffffffu, pre, 31);
    if (total > 0) {
        int wbase = 0;
        if (lane == 31) wbase = atomicAdd(&scnt, total);
        wbase = __shfl_sync(0xffffffffu, wbase, 31);
        int o = blockIdx.x * SEG + wbase + (pre - n);
        if (p0) { g_seg_val[o] = s.x; g_seg_wm[o] = m0; g_seg_idx[o] = p4;     o++; }
        if (p1) { g_seg_val[o] = s.y; g_seg_wm[o] = m1; g_seg_idx[o] = p4 + 1; o++; }
        if (p2) { g_seg_val[o] = s.z; g_seg_wm[o] = m2; g_seg_idx[o] = p4 + 2; o++; }
        if (p3) { g_seg_val[o] = s.w; g_seg_wm[o] = m3; g_seg_idx[o] = p4 + 3; }
    }

    // ---- block-exact sorted top-10 of all 1024 scores ----
    float a0 = s.x, a1 = s.y, a2 = s.z, a3 = s.w, tmp;
    if (a1 > a0) { tmp = a0; a0 = a1; a1 = tmp; }
    if (a3 > a2) { tmp = a2; a2 = a3; a3 = tmp; }
    if (a2 > a0) { tmp = a0; a0 = a2; a2 = tmp; }
    if (a3 > a1) { tmp = a1; a1 = a3; a3 = tmp; }
    if (a2 > a1) { tmp = a1; a1 = a2; a2 = tmp; }
    float st[4] = {a0, a1, a2, a3};
    warp_merge_pop<4>(st, lane, &wtop[wid * 10]);
    __syncthreads();
    if (t == 0) g_seg_cnt[blockIdx.x] = scnt;
    if (wid == 0) {
        float m[10];
#pragma unroll
        for (int k = 0; k < 10; k++)
            m[k] = (lane < 8) ? wtop[lane * 10 + k] : -INFINITY;
        warp_merge_pop<10>(m, lane, &g_part[blockIdx.x * 10]);
    }
    __syncthreads();

    // ---- ticket: last block of this batch merges the 64 top-10 lists ----
    if (t == 0) {
        __threadfence();
        s_last = (atomicAdd(&g_done[b], 1) == 63);
    }
    __syncthreads();
    if (!s_last) return;

    if (wid < 2) {
        float m[10];
        const float* src = g_part + (b * 64 + wid * 32 + lane) * 10;
#pragma unroll
        for (int k = 0; k < 10; k++) m[k] = src[k];
        warp_merge_pop<10>(m, lane, &wlist[wid][0]);
    }
    __syncthreads();
    if (wid == 0) {
        float m[10];
#pragma unroll
        for (int k = 0; k < 10; k++)
            m[k] = (lane < 2) ? wlist[lane][k] : -INFINITY;
        float t10 = warp_merge_pop<10>(m, lane, 0);
        if (lane == 0) { g_thresh[b] = t10; g_done[b] = 0; }  // replay-safe reset
    }
}

// ---------------------------------------------------------------------------
// Kernel 2: finalize. Block i processes k1-block i's candidate segment with
// the precomputed batch threshold. Sparse box writes (out pre-zeroed).
// ---------------------------------------------------------------------------
__global__ void __launch_bounds__(256) k_finalize(
    float* __restrict__ out_box, float* __restrict__ out_m) {
    int t = threadIdx.x;
    int blk = blockIdx.x;
    int b = blk >> 6;
    float t10 = g_thresh[b];
    int cnt = g_seg_cnt[blk];
    for (int i = t; i < cnt; i += 256) {
        float scv = g_seg_val[blk * SEG + i];
        float sg  = 1.0f / (1.0f + expf(-scv));
        bool m = ((scv >= t10) && (sg > 0.6f)) || (sg > 0.8f);
        if (!m) continue;
        int pix = g_seg_idx[blk * SEG + i];
        int hw = pix & (HWSZ - 1);
        float xg = (float)(hw & 255), yg = (float)(hw >> 8);
        float cw = expf(scv) * 10.0f;
        float ch = expf(g_seg_wm[blk * SEG + i]) * 10.0f;
        float x1 = floorf(xg - cw), x2 = ceilf(xg + cw);
        if (x1 < 0.0f || x2 > 256.0f) {
            float hv = fminf(256.0f - xg, xg);
            x1 = floorf(xg - hv); x2 = ceilf(xg + hv);
        }
        float y1 = floorf(yg - ch), y2 = ceilf(yg + ch);
        if (y1 < 0.0f || y2 > 256.0f) {
            float hh = fminf(256.0f - yg, yg);
            y1 = floorf(yg - hh); y2 = ceilf(yg + hh);
        }
        float* r = out_box + (size_t)pix * 5;
        r[0] = sg; r[1] = x1; r[2] = y1; r[3] = x2; r[4] = y2;
        out_m[pix] = 1.0f;
    }
}

// ---------------------------------------------------------------------------
// Launch. Output layout: score[B*HW] | out[B*HW*5] | m[B*HW]  (all f32)
// ---------------------------------------------------------------------------
extern "C" void kernel_launch(void* const* d_in, const int* in_sizes, int n_in,
                              void* d_out, int out_size) {
    const float* color   = (const float*)d_in[1];
    const float* w_bbx   = (const float*)d_in[2];
    const float* w_width = (const float*)d_in[3];
    const float* w_score = (const float*)d_in[5];

    float* score   = (float*)d_out;
    float* out_box = score + NPIX;
    float* out_m   = out_box + (size_t)NPIX * 5;

    k_score_wmap<<<1024, 256>>>(color, w_bbx, w_width, w_score, score, out_box);
    k_finalize<<<NCBLK, 256>>>(out_box, out_m);
}